// round 5
// baseline (speedup 1.0000x reference)
#include <cuda_runtime.h>
#include <stdint.h>

#define NCONCEPTS 4096
#define CDIM      1024
#define BATCH     4096
#define KSAMP     256

// Scratch (allocation-free rule: device globals).
__device__ float    g_s[NCONCEPTS];                    // 16 KB
__device__ unsigned g_mask[BATCH * (NCONCEPTS / 32)];  // 2 MB bitmask, 128 words/row

// ---------------------------------------------------------------------------
// Kernel 1 (prep): per CTA (512 CTAs):
//   a) build the 4096-bit masks for 8 batch rows (shared atomics, 4KB) and
//      write them to g_mask  — cheap, hides under (b)
//   b) s[c] = sum_d cb[c,d]*A[c,d] for 8 concept rows (one warp per row)
// ---------------------------------------------------------------------------
__global__ __launch_bounds__(256) void prep_kernel(
    const float* __restrict__ cb, const float* __restrict__ attn,
    const int* __restrict__ sampled_idx)
{
    __shared__ unsigned bm[8 * 128];   // 8 rows x 128 words = 4 KB

    const int t    = threadIdx.x;
    const int warp = t >> 5;
    const int lane = t & 31;

    // zero masks: 1024 words = 256 uint4
    reinterpret_cast<uint4*>(bm)[t] = make_uint4(0u, 0u, 0u, 0u);
    __syncthreads();

    // 8 batch rows' indices = 2048 contiguous ints = 512 int4; 2 per thread.
    {
        const int4* i4 = reinterpret_cast<const int4*>(
            sampled_idx + (size_t)blockIdx.x * 8 * KSAMP);
        #pragma unroll
        for (int j = 0; j < 2; j++) {
            int p  = t + j * 256;
            int4 v = i4[p];
            int r  = p >> 6;                 // 64 int4 per row
            int a  = v.x & (NCONCEPTS - 1);
            int b  = v.y & (NCONCEPTS - 1);
            int c  = v.z & (NCONCEPTS - 1);
            int d  = v.w & (NCONCEPTS - 1);
            atomicOr(&bm[r * 128 + (a >> 5)], 1u << (a & 31));
            atomicOr(&bm[r * 128 + (b >> 5)], 1u << (b & 31));
            atomicOr(&bm[r * 128 + (c >> 5)], 1u << (c & 31));
            atomicOr(&bm[r * 128 + (d >> 5)], 1u << (d & 31));
        }
    }

    // Row-dot: one warp per concept row (the long pole; DRAM-bound).
    {
        const int row = blockIdx.x * 8 + warp;
        const float4* c4 = reinterpret_cast<const float4*>(cb   + (size_t)row * CDIM);
        const float4* a4 = reinterpret_cast<const float4*>(attn + (size_t)row * CDIM);
        float sum = 0.f;
        #pragma unroll
        for (int i = 0; i < (CDIM / 4) / 32; i++) {
            float4 c = c4[lane + i * 32];
            float4 a = a4[lane + i * 32];
            sum += c.x * a.x + c.y * a.y + c.z * a.z + c.w * a.w;
        }
        #pragma unroll
        for (int o = 16; o > 0; o >>= 1)
            sum += __shfl_xor_sync(0xFFFFFFFFu, sum, o);
        if (lane == 0) g_s[row] = sum;
    }

    __syncthreads();   // atomics complete before mask copy-out

    // copy masks out, coalesced: 256 uint4
    reinterpret_cast<uint4*>(g_mask + (size_t)blockIdx.x * 1024)[t] =
        reinterpret_cast<const uint4*>(bm)[t];
}

// ---------------------------------------------------------------------------
// Kernel 2 (store): pure streaming — no shared, no atomics, no barriers.
// CTA = (stripe of 1024 cols) x (group of 8 rows).  grid = 4 x 512 = 2048.
// Thread: 1 LDG of its s-float4, 8 mask-word LDGs (L2-hot, 8 threads/word
// broadcast), 8 independent STG.128.
// ---------------------------------------------------------------------------
__global__ __launch_bounds__(256) void store_kernel(float* __restrict__ out)
{
    const int t      = threadIdx.x;
    const int stripe = blockIdx.x & 3;
    const int rg     = blockIdx.x >> 2;          // row group of 8
    const int col4   = stripe * 256 + t;         // float4 index within a row

    const float4 sv = reinterpret_cast<const float4*>(g_s)[col4];
    const int word  = col4 >> 3;                 // 8 float4 per 32-bit word
    const int sh    = (col4 & 7) * 4;

    const unsigned* mp = g_mask + (size_t)rg * 8 * 128 + word;
    unsigned w[8];
    #pragma unroll
    for (int r = 0; r < 8; r++) w[r] = mp[r * 128];

    float4* o4 = reinterpret_cast<float4*>(out) + (size_t)rg * 8 * 1024 + col4;
    #pragma unroll
    for (int r = 0; r < 8; r++) {
        unsigned b = w[r] >> sh;
        float4 v;
        v.x = (b & 1u) ? sv.x : 0.f;
        v.y = (b & 2u) ? sv.y : 0.f;
        v.z = (b & 4u) ? sv.z : 0.f;
        v.w = (b & 8u) ? sv.w : 0.f;
        o4[(size_t)r * 1024] = v;
    }
}

extern "C" void kernel_launch(void* const* d_in, const int* in_sizes, int n_in,
                              void* d_out, int out_size)
{
    const float* cb   = (const float*)d_in[0];
    const float* attn = (const float*)d_in[1];
    const int*   idx  = (const int*)d_in[2];
    float*       out  = (float*)d_out;

    prep_kernel<<<NCONCEPTS / 8, 256>>>(cb, attn, idx);
    store_kernel<<<2048, 256>>>(out);
}